// round 11
// baseline (speedup 1.0000x reference)
#include <cuda_runtime.h>

// Problem constants (fixed shapes for this problem)
#define N_HALF 2048
#define M_TOT  4096      // 2N
#define D_DIM  512
#define TEMP_INV 10.0f   // 1/0.1
#define GAMMA_C  0.5f    // 1/(2*sigma^2), sigma=1
#define INF_V    1.0e8f

#define BM 128
#define BN 128
#define BK 16
#define TM 8
#define TN 8
#define NTHREADS 256
#define NKT (D_DIM/BK)      // 32 k-tiles
#define NTILES (M_TOT/BN)   // 32 column tiles
#define NRB    (M_TOT/BM)   // 32 row blocks
#define NTRI   (NRB*(NRB+1)/2)   // 528 triangular tiles

// ---- device scratch (static: no runtime allocation) ----
__device__ float g_Zn[M_TOT * D_DIM];          // normalized, concatenated [4096,512]
__device__ float g_p2[M_TOT];                  // tiled positions
__device__ int   g_lab[M_TOT];                 // tiled labels (int)
__device__ float g_invS[M_TOT];                // 1 / column-sum of raw weights
__device__ float g_part[M_TOT * NTILES * 4];   // per (row, colTile): {max, sumexp, sumSW, sumW}
__device__ float g_acc;                        // final loss accumulator

// ---- f32x2 helpers (Blackwell packed fp32 FMA) ----
__device__ __forceinline__ unsigned long long pack2(float lo, float hi) {
    unsigned long long r;
    asm("mov.b64 %0, {%1, %2};" : "=l"(r) : "f"(lo), "f"(hi));
    return r;
}
__device__ __forceinline__ void unpack2(unsigned long long v, float& lo, float& hi) {
    asm("mov.b64 {%0, %1}, %2;" : "=f"(lo), "=f"(hi) : "l"(v));
}
__device__ __forceinline__ void fma2(unsigned long long& d, unsigned long long a, unsigned long long b) {
    asm("fma.rn.f32x2 %0, %1, %2, %0;" : "+l"(d) : "l"(a), "l"(b));
}

// ============================================================
// Kernel 1: normalize rows of z_i/z_j into g_Zn, fill p2/lab, zero accumulator
// grid: 4096 blocks x 128 threads
// ============================================================
__global__ void prep_kernel(const float* __restrict__ zi,
                            const float* __restrict__ zj,
                            const long long* __restrict__ labels,
                            const float* __restrict__ zpos) {
    int r = blockIdx.x;
    int tid = threadIdx.x;
    const float* src = (r < N_HALF) ? (zi + (size_t)r * D_DIM)
                                    : (zj + (size_t)(r - N_HALF) * D_DIM);
    float4 v = reinterpret_cast<const float4*>(src)[tid];  // 128*4 = 512
    float ss = v.x * v.x + v.y * v.y + v.z * v.z + v.w * v.w;
    #pragma unroll
    for (int m = 16; m >= 1; m >>= 1)
        ss += __shfl_xor_sync(0xffffffffu, ss, m);
    __shared__ float wsum[4];
    if ((tid & 31) == 0) wsum[tid >> 5] = ss;
    __syncthreads();
    float tot = wsum[0] + wsum[1] + wsum[2] + wsum[3];
    float nrm = sqrtf(tot);
    float inv = 1.0f / fmaxf(nrm, 1e-12f);
    reinterpret_cast<float4*>(&g_Zn[(size_t)r * D_DIM])[tid] =
        make_float4(v.x * inv, v.y * inv, v.z * inv, v.w * inv);
    if (tid == 0) {
        int rm = (r < N_HALF) ? r : (r - N_HALF);
        g_p2[r]  = zpos[rm];
        g_lab[r] = (int)labels[rm];
        if (r == 0) g_acc = 0.0f;
    }
}

// ============================================================
// Kernel 2: column sums S[j] = sum_i (lab match, i!=j) exp(-gamma d^2)
// grid: 4096 blocks x 256 threads
// ============================================================
__global__ void colsum_kernel() {
    int j = blockIdx.x;
    int tid = threadIdx.x;
    int labj = g_lab[j];
    float pj = g_p2[j];
    float s = 0.0f;
    for (int i = tid; i < M_TOT; i += 256) {
        if (g_lab[i] == labj && i != j) {
            float d = g_p2[i] - pj;
            s += __expf(-GAMMA_C * d * d);
        }
    }
    #pragma unroll
    for (int m = 16; m >= 1; m >>= 1)
        s += __shfl_xor_sync(0xffffffffu, s, m);
    __shared__ float wsum[8];
    if ((tid & 31) == 0) wsum[tid >> 5] = s;
    __syncthreads();
    if (tid == 0) {
        float tot = 0.0f;
        #pragma unroll
        for (int w = 0; w < 8; w++) tot += wsum[w];
        g_invS[j] = 1.0f / tot;
    }
}

// ============================================================
// Kernel 3: fused G = Z Z^T tile + softmax/weight epilogue partials.
// SYMMETRIC: 1-D grid of 528 triangular tiles (rb <= cb); off-diagonal
// tiles also emit transposed column-stats for the mirror tile.
// 256 threads; f32x2 FMAs; ping-pong double buffer; 1 barrier / k-tile.
// ============================================================
__global__ void __launch_bounds__(NTHREADS)
main_kernel() {
    // decode triangular linear index t -> (rb, cb), rb <= cb:
    // t = cb*(cb+1)/2 + rb
    const int t = blockIdx.x;
    int cb = (int)((sqrtf(8.0f * (float)t + 1.0f) - 1.0f) * 0.5f);
    while ((cb + 1) * (cb + 2) / 2 <= t) cb++;   // fixup (exact for t < 528)
    while (cb * (cb + 1) / 2 > t) cb--;
    const int rb = t - cb * (cb + 1) / 2;

    const int tid = threadIdx.x;
    const int ty = tid >> 4;     // 0..15 -> row group
    const int tx = tid & 15;     // 0..15 -> col group
    const int rowBase = rb * BM;
    const int colBase = cb * BN;

    __shared__ __align__(16) unsigned long long AsD[2][BK][BM];  // (A,A) dup
    __shared__ __align__(16) float Bs[2][BK][BN];

    // this thread's two load slots (fixed for the whole kernel)
    const int r0  = tid >> 2;                 // rows 0..63
    const int kq0 = (tid & 3) << 2;           // 0,4,8,12
    const int r1  = (tid + 256) >> 2;         // rows 64..127
    const int kq1 = kq0;

    unsigned long long acc2[TM][TN / 2];
    #pragma unroll
    for (int i = 0; i < TM; i++)
        #pragma unroll
        for (int jh = 0; jh < TN / 2; jh++)
            acc2[i][jh] = 0ull;

    // ---- prologue: load tile 0 into buffer 0 ----
    {
        float4 va0 = *reinterpret_cast<const float4*>(
            &g_Zn[(size_t)(rowBase + r0) * D_DIM + kq0]);
        float4 vb0 = *reinterpret_cast<const float4*>(
            &g_Zn[(size_t)(colBase + r0) * D_DIM + kq0]);
        float4 va1 = *reinterpret_cast<const float4*>(
            &g_Zn[(size_t)(rowBase + r1) * D_DIM + kq1]);
        float4 vb1 = *reinterpret_cast<const float4*>(
            &g_Zn[(size_t)(colBase + r1) * D_DIM + kq1]);
        AsD[0][kq0 + 0][r0] = pack2(va0.x, va0.x);
        AsD[0][kq0 + 1][r0] = pack2(va0.y, va0.y);
        AsD[0][kq0 + 2][r0] = pack2(va0.z, va0.z);
        AsD[0][kq0 + 3][r0] = pack2(va0.w, va0.w);
        Bs[0][kq0 + 0][r0] = vb0.x; Bs[0][kq0 + 1][r0] = vb0.y;
        Bs[0][kq0 + 2][r0] = vb0.z; Bs[0][kq0 + 3][r0] = vb0.w;
        AsD[0][kq1 + 0][r1] = pack2(va1.x, va1.x);
        AsD[0][kq1 + 1][r1] = pack2(va1.y, va1.y);
        AsD[0][kq1 + 2][r1] = pack2(va1.z, va1.z);
        AsD[0][kq1 + 3][r1] = pack2(va1.w, va1.w);
        Bs[0][kq1 + 0][r1] = vb1.x; Bs[0][kq1 + 1][r1] = vb1.y;
        Bs[0][kq1 + 2][r1] = vb1.z; Bs[0][kq1 + 3][r1] = vb1.w;
    }
    __syncthreads();

    for (int it = 0; it < NKT; it++) {
        const int cur = it & 1;
        float4 na0, nb0, na1, nb1;
        const bool more = (it + 1) < NKT;
        if (more) {
            int kt = (it + 1) * BK;
            na0 = *reinterpret_cast<const float4*>(
                &g_Zn[(size_t)(rowBase + r0) * D_DIM + kt + kq0]);
            nb0 = *reinterpret_cast<const float4*>(
                &g_Zn[(size_t)(colBase + r0) * D_DIM + kt + kq0]);
            na1 = *reinterpret_cast<const float4*>(
                &g_Zn[(size_t)(rowBase + r1) * D_DIM + kt + kq1]);
            nb1 = *reinterpret_cast<const float4*>(
                &g_Zn[(size_t)(colBase + r1) * D_DIM + kt + kq1]);
        }

        #pragma unroll
        for (int k = 0; k < BK; k++) {
            unsigned long long a2[TM], b2[TN / 2];
            #pragma unroll
            for (int ih = 0; ih < TM / 2; ih++) {
                ulonglong2 av = *reinterpret_cast<const ulonglong2*>(
                    &AsD[cur][k][ty * TM + 2 * ih]);
                a2[2 * ih]     = av.x;
                a2[2 * ih + 1] = av.y;
            }
            #pragma unroll
            for (int jq = 0; jq < TN / 4; jq++) {
                ulonglong2 bv = *reinterpret_cast<const ulonglong2*>(
                    &Bs[cur][k][tx * TN + 4 * jq]);
                b2[2 * jq]     = bv.x;
                b2[2 * jq + 1] = bv.y;
            }
            #pragma unroll
            for (int i = 0; i < TM; i++)
                #pragma unroll
                for (int jh = 0; jh < TN / 2; jh++)
                    fma2(acc2[i][jh], a2[i], b2[jh]);
        }

        if (more) {
            const int nxt = cur ^ 1;
            AsD[nxt][kq0 + 0][r0] = pack2(na0.x, na0.x);
            AsD[nxt][kq0 + 1][r0] = pack2(na0.y, na0.y);
            AsD[nxt][kq0 + 2][r0] = pack2(na0.z, na0.z);
            AsD[nxt][kq0 + 3][r0] = pack2(na0.w, na0.w);
            Bs[nxt][kq0 + 0][r0] = nb0.x; Bs[nxt][kq0 + 1][r0] = nb0.y;
            Bs[nxt][kq0 + 2][r0] = nb0.z; Bs[nxt][kq0 + 3][r0] = nb0.w;
            AsD[nxt][kq1 + 0][r1] = pack2(na1.x, na1.x);
            AsD[nxt][kq1 + 1][r1] = pack2(na1.y, na1.y);
            AsD[nxt][kq1 + 2][r1] = pack2(na1.z, na1.z);
            AsD[nxt][kq1 + 3][r1] = pack2(na1.w, na1.w);
            Bs[nxt][kq1 + 0][r1] = nb1.x; Bs[nxt][kq1 + 1][r1] = nb1.y;
            Bs[nxt][kq1 + 2][r1] = nb1.z; Bs[nxt][kq1 + 3][r1] = nb1.w;
            __syncthreads();
        }
    }

    // ---- epilogue part 1: direct row stats (registers + shfl only) ----
    const int row0 = rowBase + ty * TM;
    const int col0 = colBase + tx * TN;

    float pc[TN], isc[TN];
    int lc[TN];
    #pragma unroll
    for (int j = 0; j < TN; j++) {
        int gj = col0 + j;
        pc[j]  = g_p2[gj];
        lc[j]  = g_lab[gj];
        isc[j] = g_invS[gj];
    }

    #pragma unroll
    for (int i = 0; i < TM; i++) {
        int gi = row0 + i;
        float pr = g_p2[gi];
        int lr = g_lab[gi];

        float s[TN];
        #pragma unroll
        for (int jh = 0; jh < TN / 2; jh++) {
            float lo, hi;
            unpack2(acc2[i][jh], lo, hi);
            s[2 * jh]     = lo * TEMP_INV;
            s[2 * jh + 1] = hi * TEMP_INV;
        }
        float mx = -3.0e38f;
        #pragma unroll
        for (int j = 0; j < TN; j++) {
            if (gi == col0 + j) s[j] -= INF_V;   // only fires in diagonal tiles
            mx = fmaxf(mx, s[j]);
        }
        #pragma unroll
        for (int m = 8; m >= 1; m >>= 1)
            mx = fmaxf(mx, __shfl_xor_sync(0xffffffffu, mx, m));

        float se = 0.0f, sw = 0.0f, ws = 0.0f;
        #pragma unroll
        for (int j = 0; j < TN; j++) {
            se += __expf(s[j] - mx);
            int gj = col0 + j;
            float dp = pr - pc[j];
            float w = (lr == lc[j] && gi != gj)
                        ? __expf(-GAMMA_C * dp * dp) * isc[j] : 0.0f;
            sw = fmaf(s[j], w, sw);
            ws += w;
        }
        #pragma unroll
        for (int m = 8; m >= 1; m >>= 1) {
            se += __shfl_xor_sync(0xffffffffu, se, m);
            sw += __shfl_xor_sync(0xffffffffu, sw, m);
            ws += __shfl_xor_sync(0xffffffffu, ws, m);
        }
        if (tx == 0) {
            *reinterpret_cast<float4*>(
                &g_part[((size_t)gi * NTILES + cb) * 4]) =
                make_float4(mx, se, sw, ws);
        }
    }

    // ---- epilogue part 2: transposed column stats (off-diagonal only) ----
    // Emits stats for rows gj (block cb) over col-tile rb, using symmetry:
    // s(gj,gi)=s(gi,gj); weight(gj->gi) = raw(gi,gj) * invS[gi].
    if (rb != cb) {
        const int warp = tid >> 5;
        const int lane = tid & 31;
        float*  redF     = reinterpret_cast<float*>(&AsD[0][0][0]);   // [8][128]
        float4* red4     = reinterpret_cast<float4*>(&AsD[0][0][0]);  // [8][128]
        float*  colmax_s = reinterpret_cast<float*>(&Bs[0][0][0]);    // [128]

        // pass 1: per-thread column maxes over its 8 rows
        float cm[TN];
        #pragma unroll
        for (int j = 0; j < TN; j++) cm[j] = -3.0e38f;
        #pragma unroll
        for (int i = 0; i < TM; i++) {
            #pragma unroll
            for (int jh = 0; jh < TN / 2; jh++) {
                float lo, hi;
                unpack2(acc2[i][jh], lo, hi);
                cm[2 * jh]     = fmaxf(cm[2 * jh],     lo * TEMP_INV);
                cm[2 * jh + 1] = fmaxf(cm[2 * jh + 1], hi * TEMP_INV);
            }
        }
        #pragma unroll
        for (int j = 0; j < TN; j++)
            cm[j] = fmaxf(cm[j], __shfl_xor_sync(0xffffffffu, cm[j], 16));

        __syncthreads();   // main-loop smem reads all done -> safe to reuse
        if (lane < 16) {
            #pragma unroll
            for (int j = 0; j < TN; j++)
                redF[warp * 128 + lane * TN + j] = cm[j];
        }
        __syncthreads();
        if (tid < 128) {
            float m = redF[tid];
            #pragma unroll
            for (int w = 1; w < 8; w++) m = fmaxf(m, redF[w * 128 + tid]);
            colmax_s[tid] = m;
        }
        __syncthreads();

        // pass 2: exp/weighted sums using final column maxes
        float cmx[TN], cse[TN], csw[TN], cws[TN];
        #pragma unroll
        for (int j = 0; j < TN; j++) {
            cmx[j] = colmax_s[tx * TN + j];
            cse[j] = 0.0f; csw[j] = 0.0f; cws[j] = 0.0f;
        }
        #pragma unroll
        for (int i = 0; i < TM; i++) {
            int gi = row0 + i;
            float pr  = g_p2[gi];
            int   lr  = g_lab[gi];
            float isr = g_invS[gi];
            #pragma unroll
            for (int jh = 0; jh < TN / 2; jh++) {
                float lo, hi;
                unpack2(acc2[i][jh], lo, hi);
                float sv[2] = {lo * TEMP_INV, hi * TEMP_INV};
                #pragma unroll
                for (int h = 0; h < 2; h++) {
                    int j = 2 * jh + h;
                    cse[j] += __expf(sv[h] - cmx[j]);
                    float dp = pr - pc[j];
                    float w = (lr == lc[j])
                                ? __expf(-GAMMA_C * dp * dp) * isr : 0.0f;
                    csw[j] = fmaf(sv[h], w, csw[j]);
                    cws[j] += w;
                }
            }
        }
        #pragma unroll
        for (int j = 0; j < TN; j++) {
            cse[j] += __shfl_xor_sync(0xffffffffu, cse[j], 16);
            csw[j] += __shfl_xor_sync(0xffffffffu, csw[j], 16);
            cws[j] += __shfl_xor_sync(0xffffffffu, cws[j], 16);
        }
        if (lane < 16) {
            #pragma unroll
            for (int j = 0; j < TN; j++)
                red4[warp * 128 + lane * TN + j] =
                    make_float4(cse[j], csw[j], cws[j], 0.0f);
        }
        __syncthreads();
        if (tid < 128) {
            float SE = 0.0f, SW = 0.0f, WS = 0.0f;
            #pragma unroll
            for (int w = 0; w < 8; w++) {
                float4 v = red4[w * 128 + tid];
                SE += v.x; SW += v.y; WS += v.z;
            }
            int gj = colBase + tid;
            *reinterpret_cast<float4*>(
                &g_part[((size_t)gj * NTILES + rb) * 4]) =
                make_float4(colmax_s[tid], SE, SW, WS);
        }
    }
}

// ============================================================
// Kernel 4: merge per-row partials across 32 col tiles, reduce loss
// grid: 32 blocks x 128 threads (1 thread / row)
// ============================================================
__global__ void finalize_kernel() {
    int row = blockIdx.x * 128 + threadIdx.x;
    const float4* p = reinterpret_cast<const float4*>(&g_part[(size_t)row * NTILES * 4]);
    float Mx = -3.0e38f;
    #pragma unroll
    for (int cb = 0; cb < NTILES; cb++) Mx = fmaxf(Mx, p[cb].x);
    float SE = 0.0f, SW = 0.0f, WS = 0.0f;
    #pragma unroll
    for (int cb = 0; cb < NTILES; cb++) {
        float4 v = p[cb];
        SE += v.y * __expf(v.x - Mx);
        SW += v.z;
        WS += v.w;
    }
    float lse = Mx + logf(SE);
    float li = SW - lse * WS;

    __shared__ float red[128];
    red[threadIdx.x] = li;
    __syncthreads();
    for (int s2 = 64; s2 >= 1; s2 >>= 1) {
        if (threadIdx.x < s2) red[threadIdx.x] += red[threadIdx.x + s2];
        __syncthreads();
    }
    if (threadIdx.x == 0) atomicAdd(&g_acc, red[0]);
}

// ============================================================
// Kernel 5: write scalar output
// ============================================================
__global__ void writeout_kernel(float* out) {
    out[0] = -g_acc * (1.0f / (float)N_HALF);
}

extern "C" void kernel_launch(void* const* d_in, const int* in_sizes, int n_in,
                              void* d_out, int out_size) {
    const float*     zi     = (const float*)d_in[0];
    const float*     zj     = (const float*)d_in[1];
    const long long* labels = (const long long*)d_in[2];
    const float*     zpos   = (const float*)d_in[3];
    float* out = (float*)d_out;

    prep_kernel<<<M_TOT, 128>>>(zi, zj, labels, zpos);
    colsum_kernel<<<M_TOT, 256>>>();
    main_kernel<<<NTRI, NTHREADS>>>();
    finalize_kernel<<<M_TOT / 128, 128>>>();
    writeout_kernel<<<1, 1>>>(out);
}

// round 15
// speedup vs baseline: 1.0403x; 1.0403x over previous
#include <cuda_runtime.h>

// Problem constants (fixed shapes for this problem)
#define N_HALF 2048
#define M_TOT  4096      // 2N
#define D_DIM  512
#define TEMP_INV 10.0f   // 1/0.1
#define GAMMA_C  0.5f    // 1/(2*sigma^2), sigma=1
#define INF_V    1.0e8f

#define BM 128
#define BN 128
#define BK 16
#define TM 8
#define TN 8
#define NTHREADS 256
#define NKT (D_DIM/BK)      // 32 k-tiles
#define NTILES (M_TOT/BN)   // 32 column tiles
#define NRB    (M_TOT/BM)   // 32 row blocks
#define NTRI   (NRB*(NRB+1)/2)   // 528 triangular tiles

// ---- device scratch (static: no runtime allocation) ----
__device__ float g_Zn[M_TOT * D_DIM];          // normalized, concatenated [4096,512]
__device__ float g_p2[M_TOT];                  // tiled positions
__device__ int   g_lab[M_TOT];                 // tiled labels (int)
__device__ float g_invS[M_TOT];                // 1 / column-sum of raw weights
__device__ float g_part[M_TOT * NTILES * 4];   // per (row, colTile): {max, sumexp, sumSW, sumW}
__device__ float g_acc;                        // final loss accumulator

// ---- f32x2 helpers (Blackwell packed fp32 FMA) ----
__device__ __forceinline__ unsigned long long pack2(float lo, float hi) {
    unsigned long long r;
    asm("mov.b64 %0, {%1, %2};" : "=l"(r) : "f"(lo), "f"(hi));
    return r;
}
__device__ __forceinline__ void unpack2(unsigned long long v, float& lo, float& hi) {
    asm("mov.b64 {%0, %1}, %2;" : "=f"(lo), "=f"(hi) : "l"(v));
}
__device__ __forceinline__ void fma2(unsigned long long& d, unsigned long long a, unsigned long long b) {
    asm("fma.rn.f32x2 %0, %1, %2, %0;" : "+l"(d) : "l"(a), "l"(b));
}

// ============================================================
// Kernel 1: normalize rows of z_i/z_j into g_Zn, fill p2/lab, zero accumulator
// grid: 4096 blocks x 128 threads
// ============================================================
__global__ void prep_kernel(const float* __restrict__ zi,
                            const float* __restrict__ zj,
                            const long long* __restrict__ labels,
                            const float* __restrict__ zpos) {
    int r = blockIdx.x;
    int tid = threadIdx.x;
    const float* src = (r < N_HALF) ? (zi + (size_t)r * D_DIM)
                                    : (zj + (size_t)(r - N_HALF) * D_DIM);
    float4 v = reinterpret_cast<const float4*>(src)[tid];  // 128*4 = 512
    float ss = v.x * v.x + v.y * v.y + v.z * v.z + v.w * v.w;
    #pragma unroll
    for (int m = 16; m >= 1; m >>= 1)
        ss += __shfl_xor_sync(0xffffffffu, ss, m);
    __shared__ float wsum[4];
    if ((tid & 31) == 0) wsum[tid >> 5] = ss;
    __syncthreads();
    float tot = wsum[0] + wsum[1] + wsum[2] + wsum[3];
    float nrm = sqrtf(tot);
    float inv = 1.0f / fmaxf(nrm, 1e-12f);
    reinterpret_cast<float4*>(&g_Zn[(size_t)r * D_DIM])[tid] =
        make_float4(v.x * inv, v.y * inv, v.z * inv, v.w * inv);
    if (tid == 0) {
        int rm = (r < N_HALF) ? r : (r - N_HALF);
        g_p2[r]  = zpos[rm];
        g_lab[r] = (int)labels[rm];
        if (r == 0) g_acc = 0.0f;
    }
}

// ============================================================
// Kernel 2: column sums S[j] = sum_i (lab match, i!=j) exp(-gamma d^2)
// grid: 4096 blocks x 256 threads
// ============================================================
__global__ void colsum_kernel() {
    int j = blockIdx.x;
    int tid = threadIdx.x;
    int labj = g_lab[j];
    float pj = g_p2[j];
    float s = 0.0f;
    for (int i = tid; i < M_TOT; i += 256) {
        if (g_lab[i] == labj && i != j) {
            float d = g_p2[i] - pj;
            s += __expf(-GAMMA_C * d * d);
        }
    }
    #pragma unroll
    for (int m = 16; m >= 1; m >>= 1)
        s += __shfl_xor_sync(0xffffffffu, s, m);
    __shared__ float wsum[8];
    if ((tid & 31) == 0) wsum[tid >> 5] = s;
    __syncthreads();
    if (tid == 0) {
        float tot = 0.0f;
        #pragma unroll
        for (int w = 0; w < 8; w++) tot += wsum[w];
        g_invS[j] = 1.0f / tot;
    }
}

// ============================================================
// Kernel 3: fused G = Z Z^T tile + softmax/weight epilogue partials.
// SYMMETRIC: 1-D grid of 528 triangular tiles (rb <= cb); off-diagonal
// tiles also emit transposed column-stats for the mirror tile.
// 256 threads; f32x2 FMAs; ping-pong double buffer; 1 barrier / k-tile.
// __launch_bounds__(256, 2): cap regs at 128 -> guaranteed 2 CTAs/SM.
// ============================================================
__global__ void __launch_bounds__(NTHREADS, 2)
main_kernel() {
    // decode triangular linear index t -> (rb, cb), rb <= cb:
    // t = cb*(cb+1)/2 + rb
    const int t = blockIdx.x;
    int cb = (int)((sqrtf(8.0f * (float)t + 1.0f) - 1.0f) * 0.5f);
    while ((cb + 1) * (cb + 2) / 2 <= t) cb++;   // fixup (exact for t < 528)
    while (cb * (cb + 1) / 2 > t) cb--;
    const int rb = t - cb * (cb + 1) / 2;

    const int tid = threadIdx.x;
    const int ty = tid >> 4;     // 0..15 -> row group
    const int tx = tid & 15;     // 0..15 -> col group
    const int rowBase = rb * BM;
    const int colBase = cb * BN;

    __shared__ __align__(16) unsigned long long AsD[2][BK][BM];  // (A,A) dup
    __shared__ __align__(16) float Bs[2][BK][BN];

    // this thread's two load slots (fixed for the whole kernel)
    const int r0  = tid >> 2;                 // rows 0..63
    const int kq0 = (tid & 3) << 2;           // 0,4,8,12
    const int r1  = (tid + 256) >> 2;         // rows 64..127
    const int kq1 = kq0;

    unsigned long long acc2[TM][TN / 2];
    #pragma unroll
    for (int i = 0; i < TM; i++)
        #pragma unroll
        for (int jh = 0; jh < TN / 2; jh++)
            acc2[i][jh] = 0ull;

    // ---- prologue: load tile 0 into buffer 0 ----
    {
        float4 va0 = *reinterpret_cast<const float4*>(
            &g_Zn[(size_t)(rowBase + r0) * D_DIM + kq0]);
        float4 vb0 = *reinterpret_cast<const float4*>(
            &g_Zn[(size_t)(colBase + r0) * D_DIM + kq0]);
        float4 va1 = *reinterpret_cast<const float4*>(
            &g_Zn[(size_t)(rowBase + r1) * D_DIM + kq1]);
        float4 vb1 = *reinterpret_cast<const float4*>(
            &g_Zn[(size_t)(colBase + r1) * D_DIM + kq1]);
        AsD[0][kq0 + 0][r0] = pack2(va0.x, va0.x);
        AsD[0][kq0 + 1][r0] = pack2(va0.y, va0.y);
        AsD[0][kq0 + 2][r0] = pack2(va0.z, va0.z);
        AsD[0][kq0 + 3][r0] = pack2(va0.w, va0.w);
        Bs[0][kq0 + 0][r0] = vb0.x; Bs[0][kq0 + 1][r0] = vb0.y;
        Bs[0][kq0 + 2][r0] = vb0.z; Bs[0][kq0 + 3][r0] = vb0.w;
        AsD[0][kq1 + 0][r1] = pack2(va1.x, va1.x);
        AsD[0][kq1 + 1][r1] = pack2(va1.y, va1.y);
        AsD[0][kq1 + 2][r1] = pack2(va1.z, va1.z);
        AsD[0][kq1 + 3][r1] = pack2(va1.w, va1.w);
        Bs[0][kq1 + 0][r1] = vb1.x; Bs[0][kq1 + 1][r1] = vb1.y;
        Bs[0][kq1 + 2][r1] = vb1.z; Bs[0][kq1 + 3][r1] = vb1.w;
    }
    __syncthreads();

    for (int it = 0; it < NKT; it++) {
        const int cur = it & 1;
        float4 na0, nb0, na1, nb1;
        const bool more = (it + 1) < NKT;
        if (more) {
            int kt = (it + 1) * BK;
            na0 = *reinterpret_cast<const float4*>(
                &g_Zn[(size_t)(rowBase + r0) * D_DIM + kt + kq0]);
            nb0 = *reinterpret_cast<const float4*>(
                &g_Zn[(size_t)(colBase + r0) * D_DIM + kt + kq0]);
            na1 = *reinterpret_cast<const float4*>(
                &g_Zn[(size_t)(rowBase + r1) * D_DIM + kt + kq1]);
            nb1 = *reinterpret_cast<const float4*>(
                &g_Zn[(size_t)(colBase + r1) * D_DIM + kt + kq1]);
        }

        #pragma unroll
        for (int k = 0; k < BK; k++) {
            unsigned long long a2[TM], b2[TN / 2];
            #pragma unroll
            for (int ih = 0; ih < TM / 2; ih++) {
                ulonglong2 av = *reinterpret_cast<const ulonglong2*>(
                    &AsD[cur][k][ty * TM + 2 * ih]);
                a2[2 * ih]     = av.x;
                a2[2 * ih + 1] = av.y;
            }
            #pragma unroll
            for (int jq = 0; jq < TN / 4; jq++) {
                ulonglong2 bv = *reinterpret_cast<const ulonglong2*>(
                    &Bs[cur][k][tx * TN + 4 * jq]);
                b2[2 * jq]     = bv.x;
                b2[2 * jq + 1] = bv.y;
            }
            #pragma unroll
            for (int i = 0; i < TM; i++)
                #pragma unroll
                for (int jh = 0; jh < TN / 2; jh++)
                    fma2(acc2[i][jh], a2[i], b2[jh]);
        }

        if (more) {
            const int nxt = cur ^ 1;
            AsD[nxt][kq0 + 0][r0] = pack2(na0.x, na0.x);
            AsD[nxt][kq0 + 1][r0] = pack2(na0.y, na0.y);
            AsD[nxt][kq0 + 2][r0] = pack2(na0.z, na0.z);
            AsD[nxt][kq0 + 3][r0] = pack2(na0.w, na0.w);
            Bs[nxt][kq0 + 0][r0] = nb0.x; Bs[nxt][kq0 + 1][r0] = nb0.y;
            Bs[nxt][kq0 + 2][r0] = nb0.z; Bs[nxt][kq0 + 3][r0] = nb0.w;
            AsD[nxt][kq1 + 0][r1] = pack2(na1.x, na1.x);
            AsD[nxt][kq1 + 1][r1] = pack2(na1.y, na1.y);
            AsD[nxt][kq1 + 2][r1] = pack2(na1.z, na1.z);
            AsD[nxt][kq1 + 3][r1] = pack2(na1.w, na1.w);
            Bs[nxt][kq1 + 0][r1] = nb1.x; Bs[nxt][kq1 + 1][r1] = nb1.y;
            Bs[nxt][kq1 + 2][r1] = nb1.z; Bs[nxt][kq1 + 3][r1] = nb1.w;
            __syncthreads();
        }
    }

    // ---- epilogue part 1: direct row stats (registers + shfl only) ----
    const int row0 = rowBase + ty * TM;
    const int col0 = colBase + tx * TN;

    float pc[TN], isc[TN];
    int lc[TN];
    #pragma unroll
    for (int j = 0; j < TN; j++) {
        int gj = col0 + j;
        pc[j]  = g_p2[gj];
        lc[j]  = g_lab[gj];
        isc[j] = g_invS[gj];
    }

    #pragma unroll
    for (int i = 0; i < TM; i++) {
        int gi = row0 + i;
        float pr = g_p2[gi];
        int lr = g_lab[gi];

        float s[TN];
        #pragma unroll
        for (int jh = 0; jh < TN / 2; jh++) {
            float lo, hi;
            unpack2(acc2[i][jh], lo, hi);
            s[2 * jh]     = lo * TEMP_INV;
            s[2 * jh + 1] = hi * TEMP_INV;
        }
        float mx = -3.0e38f;
        #pragma unroll
        for (int j = 0; j < TN; j++) {
            if (gi == col0 + j) s[j] -= INF_V;   // only fires in diagonal tiles
            mx = fmaxf(mx, s[j]);
        }
        #pragma unroll
        for (int m = 8; m >= 1; m >>= 1)
            mx = fmaxf(mx, __shfl_xor_sync(0xffffffffu, mx, m));

        float se = 0.0f, sw = 0.0f, ws = 0.0f;
        #pragma unroll
        for (int j = 0; j < TN; j++) {
            se += __expf(s[j] - mx);
            int gj = col0 + j;
            float dp = pr - pc[j];
            float w = (lr == lc[j] && gi != gj)
                        ? __expf(-GAMMA_C * dp * dp) * isc[j] : 0.0f;
            sw = fmaf(s[j], w, sw);
            ws += w;
        }
        #pragma unroll
        for (int m = 8; m >= 1; m >>= 1) {
            se += __shfl_xor_sync(0xffffffffu, se, m);
            sw += __shfl_xor_sync(0xffffffffu, sw, m);
            ws += __shfl_xor_sync(0xffffffffu, ws, m);
        }
        if (tx == 0) {
            *reinterpret_cast<float4*>(
                &g_part[((size_t)gi * NTILES + cb) * 4]) =
                make_float4(mx, se, sw, ws);
        }
    }

    // ---- epilogue part 2: transposed column stats (off-diagonal only) ----
    // Emits stats for rows gj (block cb) over col-tile rb, using symmetry:
    // s(gj,gi)=s(gi,gj); weight(gj->gi) = raw(gi,gj) * invS[gi].
    if (rb != cb) {
        const int warp = tid >> 5;
        const int lane = tid & 31;
        float*  redF     = reinterpret_cast<float*>(&AsD[0][0][0]);   // [8][128]
        float4* red4     = reinterpret_cast<float4*>(&AsD[0][0][0]);  // [8][128]
        float*  colmax_s = reinterpret_cast<float*>(&Bs[0][0][0]);    // [128]

        // pass 1: per-thread column maxes over its 8 rows
        float cm[TN];
        #pragma unroll
        for (int j = 0; j < TN; j++) cm[j] = -3.0e38f;
        #pragma unroll
        for (int i = 0; i < TM; i++) {
            #pragma unroll
            for (int jh = 0; jh < TN / 2; jh++) {
                float lo, hi;
                unpack2(acc2[i][jh], lo, hi);
                cm[2 * jh]     = fmaxf(cm[2 * jh],     lo * TEMP_INV);
                cm[2 * jh + 1] = fmaxf(cm[2 * jh + 1], hi * TEMP_INV);
            }
        }
        #pragma unroll
        for (int j = 0; j < TN; j++)
            cm[j] = fmaxf(cm[j], __shfl_xor_sync(0xffffffffu, cm[j], 16));

        __syncthreads();   // main-loop smem reads all done -> safe to reuse
        if (lane < 16) {
            #pragma unroll
            for (int j = 0; j < TN; j++)
                redF[warp * 128 + lane * TN + j] = cm[j];
        }
        __syncthreads();
        if (tid < 128) {
            float m = redF[tid];
            #pragma unroll
            for (int w = 1; w < 8; w++) m = fmaxf(m, redF[w * 128 + tid]);
            colmax_s[tid] = m;
        }
        __syncthreads();

        // pass 2: exp/weighted sums using final column maxes
        float cmx[TN], cse[TN], csw[TN], cws[TN];
        #pragma unroll
        for (int j = 0; j < TN; j++) {
            cmx[j] = colmax_s[tx * TN + j];
            cse[j] = 0.0f; csw[j] = 0.0f; cws[j] = 0.0f;
        }
        #pragma unroll
        for (int i = 0; i < TM; i++) {
            int gi = row0 + i;
            float pr  = g_p2[gi];
            int   lr  = g_lab[gi];
            float isr = g_invS[gi];
            #pragma unroll
            for (int jh = 0; jh < TN / 2; jh++) {
                float lo, hi;
                unpack2(acc2[i][jh], lo, hi);
                float sv[2] = {lo * TEMP_INV, hi * TEMP_INV};
                #pragma unroll
                for (int h = 0; h < 2; h++) {
                    int j = 2 * jh + h;
                    cse[j] += __expf(sv[h] - cmx[j]);
                    float dp = pr - pc[j];
                    float w = (lr == lc[j])
                                ? __expf(-GAMMA_C * dp * dp) * isr : 0.0f;
                    csw[j] = fmaf(sv[h], w, csw[j]);
                    cws[j] += w;
                }
            }
        }
        #pragma unroll
        for (int j = 0; j < TN; j++) {
            cse[j] += __shfl_xor_sync(0xffffffffu, cse[j], 16);
            csw[j] += __shfl_xor_sync(0xffffffffu, csw[j], 16);
            cws[j] += __shfl_xor_sync(0xffffffffu, cws[j], 16);
        }
        if (lane < 16) {
            #pragma unroll
            for (int j = 0; j < TN; j++)
                red4[warp * 128 + lane * TN + j] =
                    make_float4(cse[j], csw[j], cws[j], 0.0f);
        }
        __syncthreads();
        if (tid < 128) {
            float SE = 0.0f, SW = 0.0f, WS = 0.0f;
            #pragma unroll
            for (int w = 0; w < 8; w++) {
                float4 v = red4[w * 128 + tid];
                SE += v.x; SW += v.y; WS += v.z;
            }
            int gj = colBase + tid;
            *reinterpret_cast<float4*>(
                &g_part[((size_t)gj * NTILES + rb) * 4]) =
                make_float4(colmax_s[tid], SE, SW, WS);
        }
    }
}

// ============================================================
// Kernel 4: merge per-row partials across 32 col tiles, reduce loss
// grid: 32 blocks x 128 threads (1 thread / row)
// ============================================================
__global__ void finalize_kernel() {
    int row = blockIdx.x * 128 + threadIdx.x;
    const float4* p = reinterpret_cast<const float4*>(&g_part[(size_t)row * NTILES * 4]);
    float Mx = -3.0e38f;
    #pragma unroll
    for (int cb = 0; cb < NTILES; cb++) Mx = fmaxf(Mx, p[cb].x);
    float SE = 0.0f, SW = 0.0f, WS = 0.0f;
    #pragma unroll
    for (int cb = 0; cb < NTILES; cb++) {
        float4 v = p[cb];
        SE += v.y * __expf(v.x - Mx);
        SW += v.z;
        WS += v.w;
    }
    float lse = Mx + logf(SE);
    float li = SW - lse * WS;

    __shared__ float red[128];
    red[threadIdx.x] = li;
    __syncthreads();
    for (int s2 = 64; s2 >= 1; s2 >>= 1) {
        if (threadIdx.x < s2) red[threadIdx.x] += red[threadIdx.x + s2];
        __syncthreads();
    }
    if (threadIdx.x == 0) atomicAdd(&g_acc, red[0]);
}

// ============================================================
// Kernel 5: write scalar output
// ============================================================
__global__ void writeout_kernel(float* out) {
    out[0] = -g_acc * (1.0f / (float)N_HALF);
}

extern "C" void kernel_launch(void* const* d_in, const int* in_sizes, int n_in,
                              void* d_out, int out_size) {
    const float*     zi     = (const float*)d_in[0];
    const float*     zj     = (const float*)d_in[1];
    const long long* labels = (const long long*)d_in[2];
    const float*     zpos   = (const float*)d_in[3];
    float* out = (float*)d_out;

    prep_kernel<<<M_TOT, 128>>>(zi, zj, labels, zpos);
    colsum_kernel<<<M_TOT, 256>>>();
    main_kernel<<<NTRI, NTHREADS>>>();
    finalize_kernel<<<M_TOT / 128, 128>>>();
    writeout_kernel<<<1, 1>>>(out);
}